// round 10
// baseline (speedup 1.0000x reference)
#include <cuda_runtime.h>

#define NN  1024
#define RAW 128
#define DD  128
#define HH  256

#define SELU_ALPHA 1.6732632423543772f
#define SELU_SCALE 1.0507009873554805f

typedef unsigned long long ull;

#define UNPACK2(lo, hi, s) asm("mov.b64 {%0, %1}, %2;" : "=f"(lo), "=f"(hi) : "l"(s))

// Scratch (static __device__ arrays; no allocation)
__device__ float  g_AT  [HH * NN];   // A^T (incl. b1)            [k][j]
__device__ float  g_EAT [HH * NN];   // exp(A^T)                  [k][j]
__device__ float  g_BT  [HH * NN];   // B^T                       [k][i]
__device__ float  g_EBT [HH * NN];   // exp(B^T)                  [k][i]
__device__ float  g_P   [NN];        // P[j] = sum_k (sw_k/2) A[k][j]
__device__ float  g_Q   [NN];        // Q[i] = sum_k (sw_k/2) B[k][i]
__device__ float4 g_hwaw[HH];        // {sw/2, sw/2, asw, asw}
__device__ float  g_c0;              // b2 - sum asw

// ---------------------------------------------------------------------------
// Fused aux (unchanged from R9): prep + z + A/B GEMMs + exp + transposed
// stores + P/Q.  256 blocks x 256 threads, 4 rows/blk.
// ---------------------------------------------------------------------------
__global__ __launch_bounds__(256) void aux_kernel(
        const float* __restrict__ x,     const float* __restrict__ W_enc,
        const float* __restrict__ b_enc, const float* __restrict__ W1,
        const float* __restrict__ b1,    const float* __restrict__ W2,
        const float* __restrict__ b2) {
    __shared__ float sx [4][RAW];
    __shared__ float sz [4][DD];
    __shared__ float swa[16 * 256];
    __shared__ float swb[16 * 256];
    __shared__ float stV[HH * 5];
    __shared__ float stE[HH * 5];
    __shared__ float redR[8][4];

    const int t  = threadIdx.x;          // k in [0,256)
    const int j0 = blockIdx.x * 4;

    if (blockIdx.x == 0) {
        float w   = W2[t];
        float sw  = SELU_SCALE * w;
        float asw = SELU_ALPHA * sw;
        float hw  = 0.5f * sw;
        g_hwaw[t] = make_float4(hw, hw, asw, asw);
        stV[t] = asw;
        __syncthreads();
        #pragma unroll
        for (int s = 128; s > 0; s >>= 1) {
            if (t < s) stV[t] += stV[t + s];
            __syncthreads();
        }
        if (t == 0) g_c0 = b2[0] - stV[0];
        __syncthreads();
    }

    #pragma unroll
    for (int s = 0; s < 2; s++) {
        int idx = t + s * 256;
        sx[idx >> 7][idx & 127] = x[(j0 + (idx >> 7)) * RAW + (idx & 127)];
    }
    __syncthreads();

    {
        const int k  = t & 127;
        const int rh = t >> 7;
        float za0 = 0.f, za1 = 0.f;
        for (int c0 = 0; c0 < RAW; c0 += 16) {
            const float4* src = reinterpret_cast<const float4*>(W_enc + c0 * DD);
            float4* dst = reinterpret_cast<float4*>(swa);
            dst[t]       = src[t];
            dst[t + 256] = src[t + 256];
            __syncthreads();
            #pragma unroll
            for (int cc = 0; cc < 16; cc++) {
                float w = swa[cc * DD + k];
                za0 = fmaf(sx[2 * rh][c0 + cc],     w, za0);
                za1 = fmaf(sx[2 * rh + 1][c0 + cc], w, za1);
            }
            __syncthreads();
        }
        float bb = b_enc[k];
        sz[2 * rh][k]     = za0 + bb;
        sz[2 * rh + 1][k] = za1 + bb;
    }
    __syncthreads();

    float accA[4] = {0.f, 0.f, 0.f, 0.f};
    float accB[4] = {0.f, 0.f, 0.f, 0.f};
    for (int c0 = 0; c0 < DD; c0 += 16) {
        const float4* srcA = reinterpret_cast<const float4*>(W1 + c0 * HH);
        const float4* srcB = reinterpret_cast<const float4*>(W1 + (c0 + DD) * HH);
        float4* dstA = reinterpret_cast<float4*>(swa);
        float4* dstB = reinterpret_cast<float4*>(swb);
        #pragma unroll
        for (int s = 0; s < 4; s++) {
            dstA[t + s * 256] = srcA[t + s * 256];
            dstB[t + s * 256] = srcB[t + s * 256];
        }
        __syncthreads();
        #pragma unroll
        for (int cc = 0; cc < 16; cc++) {
            float wa = swa[cc * HH + t];
            float wb = swb[cc * HH + t];
            #pragma unroll
            for (int r = 0; r < 4; r++) {
                float zz = sz[r][c0 + cc];
                accA[r] = fmaf(zz, wa, accA[r]);
                accB[r] = fmaf(zz, wb, accB[r]);
            }
        }
        __syncthreads();
    }

    const float b1k = b1[t];
    const float hw  = 0.5f * SELU_SCALE * W2[t];
    const int wid = t >> 5, lid = t & 31;

    // ---- round A: AT/EAT stores + P ----
    {
        float pv[4];
        #pragma unroll
        for (int r = 0; r < 4; r++) {
            float a = accA[r] + b1k;
            stV[t * 5 + r] = a;
            stE[t * 5 + r] = __expf(fminf(fmaxf(a, -60.f), 60.f));
            pv[r] = hw * a;
        }
        #pragma unroll
        for (int r = 0; r < 4; r++) {
            float v = pv[r];
            #pragma unroll
            for (int s = 16; s > 0; s >>= 1)
                v += __shfl_down_sync(0xffffffffu, v, s);
            if (lid == 0) redR[wid][r] = v;
        }
        __syncthreads();
        #pragma unroll
        for (int p = 0; p < 4; p++) {
            int idx = p * 256 + t;
            int k = idx >> 2, j = idx & 3;
            g_AT [k * NN + j0 + j] = stV[k * 5 + j];
            g_EAT[k * NN + j0 + j] = stE[k * 5 + j];
        }
        if (t < 4) {
            float s = 0.f;
            #pragma unroll
            for (int w2i = 0; w2i < 8; w2i++) s += redR[w2i][t];
            g_P[j0 + t] = s;
        }
        __syncthreads();
    }

    // ---- round B: BT/EBT stores + Q ----
    {
        float pv[4];
        #pragma unroll
        for (int r = 0; r < 4; r++) {
            float b = accB[r];
            stV[t * 5 + r] = b;
            stE[t * 5 + r] = __expf(fminf(fmaxf(b, -60.f), 60.f));
            pv[r] = hw * b;
        }
        #pragma unroll
        for (int r = 0; r < 4; r++) {
            float v = pv[r];
            #pragma unroll
            for (int s = 16; s > 0; s >>= 1)
                v += __shfl_down_sync(0xffffffffu, v, s);
            if (lid == 0) redR[wid][r] = v;
        }
        __syncthreads();
        #pragma unroll
        for (int p = 0; p < 4; p++) {
            int idx = p * 256 + t;
            int k = idx >> 2, j = idx & 3;
            g_BT [k * NN + j0 + j] = stV[k * 5 + j];
            g_EBT[k * NN + j0 + j] = stE[k * 5 + j];
        }
        if (t < 4) {
            float s = 0.f;
            #pragma unroll
            for (int w2i = 0; w2i < 8; w2i++) s += redR[w2i][t];
            g_Q[j0 + t] = s;
        }
    }
}

// ---------------------------------------------------------------------------
// Main: o[i,j] = hsig( P[j] + Q[i] + c0 + sum_k [ hw_k*|v| + asw_k*sat(e) ] )
//   v = A[k][j]+B[k][i], e = EA[k][j]*EB[k][i] = exp(v), sat(e) = min(e,1).
// R9 skeleton (64x64 tiles, 256 thr, 4x4/thread, register prefetch, LDG/STS)
// with minimized FMA-pipe count: packed relu half + packed-accumulate e half,
// B dup-packed at STS time, weights read as raw ull halves.  40 FMA-pipe ops
// per 16 elements per thread.
// ---------------------------------------------------------------------------
__global__ __launch_bounds__(256, 2) void main_kernel(float* __restrict__ out) {
    __shared__ float4 s_a [16][16];   // [k][j4]
    __shared__ float4 s_ea[16][16];
    __shared__ ull    s_bd[16][64];   // [k][i] dup pairs {b,b}
    __shared__ float4 s_eb[16][16];   // [k][i4]
    __shared__ float4 s_wa[16];       // {hw,hw,asw,asw}

    const int tid = threadIdx.x;
    const int tx  = tid & 15;    // j quad
    const int ty  = tid >> 4;    // i quad
    const int j0  = blockIdx.x * 64;
    const int i0  = blockIdx.y * 64;

    const float4* AT4  = reinterpret_cast<const float4*>(g_AT);
    const float4* EAT4 = reinterpret_cast<const float4*>(g_EAT);
    const float4* BT4  = reinterpret_cast<const float4*>(g_BT);
    const float4* EBT4 = reinterpret_cast<const float4*>(g_EBT);

    const int ar = tid >> 4, ac = tid & 15;   // tile loader coords
    const ull MASK = 0x7FFFFFFF7FFFFFFFull;

    const int gja = ar * (NN / 4) + (j0 >> 2) + ac;
    const int gib = ar * (NN / 4) + (i0 >> 2) + ac;

    ull accP[4][2];
    ull accE[4][2];
    #pragma unroll
    for (int i = 0; i < 4; i++) {
        accP[i][0] = 0ull; accP[i][1] = 0ull;
        accE[i][0] = 0ull; accE[i][1] = 0ull;
    }

    // prefetch chunk 0 into registers
    float4 pa, pea, pb, peb, pwa;
    pa  = AT4 [gja];
    pea = EAT4[gja];
    pb  = BT4 [gib];
    peb = EBT4[gib];
    if (tid < 16) pwa = g_hwaw[tid];

    for (int c = 0; c < 16; c++) {
        __syncthreads();
        s_a [ar][ac] = pa;
        s_ea[ar][ac] = pea;
        s_eb[ar][ac] = peb;
        // dup-pack B at store time: {x,x,y,y} and {z,z,w,w}
        {
            float4* bd4 = reinterpret_cast<float4*>(&s_bd[ar][ac * 4]);
            bd4[0] = make_float4(pb.x, pb.x, pb.y, pb.y);
            bd4[1] = make_float4(pb.z, pb.z, pb.w, pb.w);
        }
        if (tid < 16) s_wa[tid] = pwa;
        __syncthreads();

        if (c < 15) {
            int oa = (c + 1) * 16 * (NN / 4);
            pa  = AT4 [gja + oa];
            pea = EAT4[gja + oa];
            pb  = BT4 [gib + oa];
            peb = EBT4[gib + oa];
            if (tid < 16) pwa = g_hwaw[(c + 1) * 16 + tid];
        }

        #pragma unroll
        for (int kk = 0; kk < 16; kk++) {
            ulonglong2 a2  = *reinterpret_cast<const ulonglong2*>(&s_a [kk][tx]);
            float4     ea  = s_ea[kk][tx];
            ulonglong2 bdA = *reinterpret_cast<const ulonglong2*>(&s_bd[kk][ty * 4]);
            ulonglong2 bdB = *reinterpret_cast<const ulonglong2*>(&s_bd[kk][ty * 4 + 2]);
            float4     eb  = s_eb[kk][ty];
            ulonglong2 wa  = *reinterpret_cast<const ulonglong2*>(&s_wa[kk]);
            const ull w2 = wa.x, aw2 = wa.y;

            ull   ap[2]  = {a2.x, a2.y};
            ull   bp[4]  = {bdA.x, bdA.y, bdB.x, bdB.y};
            float eav[4] = {ea.x, ea.y, ea.z, ea.w};
            float ebv[4] = {eb.x, eb.y, eb.z, eb.w};

            #pragma unroll
            for (int i = 0; i < 4; i++) {
                #pragma unroll
                for (int jp = 0; jp < 2; jp++) {
                    asm("{\n\t"
                        ".reg .b64 v, e;\n\t"
                        ".reg .f32 e0, e1;\n\t"
                        "add.rn.f32x2 v, %2, %3;\n\t"
                        "and.b64 v, v, %4;\n\t"
                        "fma.rn.f32x2 %0, v, %5, %0;\n\t"
                        "mul.rn.sat.f32 e0, %6, %8;\n\t"
                        "mul.rn.sat.f32 e1, %7, %8;\n\t"
                        "mov.b64 e, {e0, e1};\n\t"
                        "fma.rn.f32x2 %1, e, %9, %1;\n\t"
                        "}"
                        : "+l"(accP[i][jp]), "+l"(accE[i][jp])
                        : "l"(ap[jp]), "l"(bp[i]), "l"(MASK), "l"(w2),
                          "f"(eav[2 * jp]), "f"(eav[2 * jp + 1]),
                          "f"(ebv[i]), "l"(aw2));
                }
            }
        }
    }

    // epilogue: + P[j] + Q[i] + c0, hard_sigmoid
    const float c0 = g_c0;
    float4 Pv = *reinterpret_cast<const float4*>(&g_P[j0 + tx * 4]);
    #pragma unroll
    for (int i = 0; i < 4; i++) {
        int   irow = i0 + ty * 4 + i;
        float base = g_Q[irow] + c0 + 3.0f;
        float p0, p1, p2, p3, e0, e1, e2, e3;
        UNPACK2(p0, p1, accP[i][0]);
        UNPACK2(p2, p3, accP[i][1]);
        UNPACK2(e0, e1, accE[i][0]);
        UNPACK2(e2, e3, accE[i][1]);
        float4 o;
        o.x = fminf(fmaxf(p0 + e0 + Pv.x + base, 0.f), 6.f) * (1.f / 6.f);
        o.y = fminf(fmaxf(p1 + e1 + Pv.y + base, 0.f), 6.f) * (1.f / 6.f);
        o.z = fminf(fmaxf(p2 + e2 + Pv.z + base, 0.f), 6.f) * (1.f / 6.f);
        o.w = fminf(fmaxf(p3 + e3 + Pv.w + base, 0.f), 6.f) * (1.f / 6.f);
        *reinterpret_cast<float4*>(&out[irow * NN + j0 + tx * 4]) = o;
    }
}

// ---------------------------------------------------------------------------
extern "C" void kernel_launch(void* const* d_in, const int* in_sizes, int n_in,
                              void* d_out, int out_size) {
    const float* x     = (const float*)d_in[0];
    const float* W_enc = (const float*)d_in[1];
    const float* b_enc = (const float*)d_in[2];
    const float* W1    = (const float*)d_in[3];
    const float* b1    = (const float*)d_in[4];
    const float* W2    = (const float*)d_in[5];
    const float* b2    = (const float*)d_in[6];
    float* out = (float*)d_out;

    aux_kernel<<<NN / 4, 256>>>(x, W_enc, b_enc, W1, b1, W2, b2);

    dim3 grid(NN / 64, NN / 64);
    main_kernel<<<grid, 256>>>(out);
}

// round 11
// speedup vs baseline: 1.1816x; 1.1816x over previous
#include <cuda_runtime.h>
#include <cuda_fp16.h>

#define NN  1024
#define RAW 128
#define DD  128
#define HH  256

#define SELU_ALPHA 1.6732632423543772f
#define SELU_SCALE 1.0507009873554805f

typedef unsigned long long ull;

// Scratch (static __device__ arrays; no allocation)
__device__ __half  g_Ah  [HH * NN];   // A^T fp16                 [k][j]
__device__ __half  g_EAh [HH * NN];   // exp(A^T) fp16            [k][j]
__device__ __half2 g_Bdh [HH * NN];   // {B,B} dup fp16           [k][i]
__device__ __half2 g_EBdh[HH * NN];   // {expB,expB} dup fp16     [k][i]
__device__ float   g_P   [NN];        // P[j] = sum_k hw_k A[k][j]
__device__ float   g_Q   [NN];        // Q[i] = sum_k hw_k B[k][i]
__device__ __half2 g_wh  [HH * 2];    // [k][0]={hw,hw} [k][1]={asw,asw}
__device__ float   g_c0;              // b2 - sum asw

// ---------------------------------------------------------------------------
// Fused aux: prep (block 0) + z + A/B GEMMs (smem-staged weights) + exp +
// transposed fp16 stores + P/Q rank-1 terms.  256 blocks x 256 threads.
// ---------------------------------------------------------------------------
__global__ __launch_bounds__(256) void aux_kernel(
        const float* __restrict__ x,     const float* __restrict__ W_enc,
        const float* __restrict__ b_enc, const float* __restrict__ W1,
        const float* __restrict__ b1,    const float* __restrict__ W2,
        const float* __restrict__ b2) {
    __shared__ float sx [4][RAW];
    __shared__ float sz [4][DD];
    __shared__ float swa[16 * 256];
    __shared__ float swb[16 * 256];
    __shared__ float stV[HH * 5];
    __shared__ float stE[HH * 5];
    __shared__ float redR[8][4];

    const int t  = threadIdx.x;          // k in [0,256)
    const int j0 = blockIdx.x * 4;

    if (blockIdx.x == 0) {
        float w   = W2[t];
        float sw  = SELU_SCALE * w;
        float asw = SELU_ALPHA * sw;
        // round hw through fp16 so the relu-cancellation with P/Q is exact
        float hwr = __half2float(__float2half(0.5f * sw));
        g_wh[2 * t]     = __float2half2_rn(hwr);
        g_wh[2 * t + 1] = __float2half2_rn(asw);
        stV[t] = asw;
        __syncthreads();
        #pragma unroll
        for (int s = 128; s > 0; s >>= 1) {
            if (t < s) stV[t] += stV[t + s];
            __syncthreads();
        }
        if (t == 0) g_c0 = b2[0] - stV[0];
        __syncthreads();
    }

    #pragma unroll
    for (int s = 0; s < 2; s++) {
        int idx = t + s * 256;
        sx[idx >> 7][idx & 127] = x[(j0 + (idx >> 7)) * RAW + (idx & 127)];
    }
    __syncthreads();

    {
        const int k  = t & 127;
        const int rh = t >> 7;
        float za0 = 0.f, za1 = 0.f;
        for (int c0 = 0; c0 < RAW; c0 += 16) {
            const float4* src = reinterpret_cast<const float4*>(W_enc + c0 * DD);
            float4* dst = reinterpret_cast<float4*>(swa);
            dst[t]       = src[t];
            dst[t + 256] = src[t + 256];
            __syncthreads();
            #pragma unroll
            for (int cc = 0; cc < 16; cc++) {
                float w = swa[cc * DD + k];
                za0 = fmaf(sx[2 * rh][c0 + cc],     w, za0);
                za1 = fmaf(sx[2 * rh + 1][c0 + cc], w, za1);
            }
            __syncthreads();
        }
        float bb = b_enc[k];
        sz[2 * rh][k]     = za0 + bb;
        sz[2 * rh + 1][k] = za1 + bb;
    }
    __syncthreads();

    float accA[4] = {0.f, 0.f, 0.f, 0.f};
    float accB[4] = {0.f, 0.f, 0.f, 0.f};
    for (int c0 = 0; c0 < DD; c0 += 16) {
        const float4* srcA = reinterpret_cast<const float4*>(W1 + c0 * HH);
        const float4* srcB = reinterpret_cast<const float4*>(W1 + (c0 + DD) * HH);
        float4* dstA = reinterpret_cast<float4*>(swa);
        float4* dstB = reinterpret_cast<float4*>(swb);
        #pragma unroll
        for (int s = 0; s < 4; s++) {
            dstA[t + s * 256] = srcA[t + s * 256];
            dstB[t + s * 256] = srcB[t + s * 256];
        }
        __syncthreads();
        #pragma unroll
        for (int cc = 0; cc < 16; cc++) {
            float wa = swa[cc * HH + t];
            float wb = swb[cc * HH + t];
            #pragma unroll
            for (int r = 0; r < 4; r++) {
                float zz = sz[r][c0 + cc];
                accA[r] = fmaf(zz, wa, accA[r]);
                accB[r] = fmaf(zz, wb, accB[r]);
            }
        }
        __syncthreads();
    }

    const float b1k = b1[t];
    const float hw  = __half2float(__float2half(0.5f * SELU_SCALE * W2[t]));
    const int wid = t >> 5, lid = t & 31;

    // ---- round A: Ah/EAh fp16 stores + P ----
    {
        float pv[4];
        #pragma unroll
        for (int r = 0; r < 4; r++) {
            float a = accA[r] + b1k;
            stV[t * 5 + r] = a;
            stE[t * 5 + r] = __expf(fminf(fmaxf(a, -8.f), 8.f));
            pv[r] = hw * a;
        }
        #pragma unroll
        for (int r = 0; r < 4; r++) {
            float v = pv[r];
            #pragma unroll
            for (int s = 16; s > 0; s >>= 1)
                v += __shfl_down_sync(0xffffffffu, v, s);
            if (lid == 0) redR[wid][r] = v;
        }
        __syncthreads();
        #pragma unroll
        for (int p = 0; p < 4; p++) {
            int idx = p * 256 + t;
            int k = idx >> 2, j = idx & 3;
            g_Ah [k * NN + j0 + j] = __float2half(stV[k * 5 + j]);
            g_EAh[k * NN + j0 + j] = __float2half(stE[k * 5 + j]);
        }
        if (t < 4) {
            float s = 0.f;
            #pragma unroll
            for (int w2i = 0; w2i < 8; w2i++) s += redR[w2i][t];
            g_P[j0 + t] = s;
        }
        __syncthreads();
    }

    // ---- round B: Bdh/EBdh dup fp16 stores + Q ----
    {
        float pv[4];
        #pragma unroll
        for (int r = 0; r < 4; r++) {
            float b = accB[r];
            stV[t * 5 + r] = b;
            stE[t * 5 + r] = __expf(fminf(fmaxf(b, -8.f), 8.f));
            pv[r] = hw * b;
        }
        #pragma unroll
        for (int r = 0; r < 4; r++) {
            float v = pv[r];
            #pragma unroll
            for (int s = 16; s > 0; s >>= 1)
                v += __shfl_down_sync(0xffffffffu, v, s);
            if (lid == 0) redR[wid][r] = v;
        }
        __syncthreads();
        #pragma unroll
        for (int p = 0; p < 4; p++) {
            int idx = p * 256 + t;
            int k = idx >> 2, j = idx & 3;
            __half hb = __float2half(stV[k * 5 + j]);
            __half he = __float2half(stE[k * 5 + j]);
            g_Bdh [k * NN + j0 + j] = __halves2half2(hb, hb);
            g_EBdh[k * NN + j0 + j] = __halves2half2(he, he);
        }
        if (t < 4) {
            float s = 0.f;
            #pragma unroll
            for (int w2i = 0; w2i < 8; w2i++) s += redR[w2i][t];
            g_Q[j0 + t] = s;
        }
    }
}

// ---------------------------------------------------------------------------
// Main: o[i,j] = hsig( P[j] + Q[i] + c0 + sum_k [ hw_k*|v| + asw_k*sat(e) ] )
//   v = A[k][j]+B[k][i] (fp16), e = EA*EB with .sat == min(e,1) (inf-safe).
// 64x64 tiles, 256 thr, 4x4/thread, register prefetch, fp16x2 core:
// HADD2 / HABS2 / HFMA2 / HMUL2.SAT / HFMA2 = 4 fma-pipe ops per 2 elements.
// fp16 accumulators flushed to fp32 every 8 k.
// ---------------------------------------------------------------------------
__global__ __launch_bounds__(256, 2) void main_kernel(float* __restrict__ out) {
    __shared__ uint2   s_a  [16][16];   // [k][j4]  4 halves
    __shared__ uint2   s_ea [16][16];
    __shared__ uint4   s_bd [16][16];   // [k][i4]  4 dup half2
    __shared__ uint4   s_ebd[16][16];
    __shared__ uint2   s_w  [16];       // {hw2, aw2}

    const int tid = threadIdx.x;
    const int tx  = tid & 15;    // j quad
    const int ty  = tid >> 4;    // i quad
    const int j0  = blockIdx.x * 64;
    const int i0  = blockIdx.y * 64;

    const uint2* Ah2  = reinterpret_cast<const uint2*>(g_Ah);
    const uint2* EAh2 = reinterpret_cast<const uint2*>(g_EAh);
    const uint4* Bd4  = reinterpret_cast<const uint4*>(g_Bdh);
    const uint4* EBd4 = reinterpret_cast<const uint4*>(g_EBdh);
    const uint2* Wh2  = reinterpret_cast<const uint2*>(g_wh);

    const int ar = tid >> 4, ac = tid & 15;   // loader coords

    const int gja = ar * (NN / 4) + (j0 >> 2) + ac;   // uint2 index (4 halves)
    const int gib = ar * (NN / 4) + (i0 >> 2) + ac;   // uint4 index (4 half2)

    float accF[4][4];
    #pragma unroll
    for (int i = 0; i < 4; i++)
        #pragma unroll
        for (int j = 0; j < 4; j++) accF[i][j] = 0.f;

    // prefetch chunk 0
    uint2 pa, pea, pw;
    uint4 pb, peb;
    pa  = Ah2 [gja];
    pea = EAh2[gja];
    pb  = Bd4 [gib];
    peb = EBd4[gib];
    if (tid < 16) pw = Wh2[tid];

    for (int c = 0; c < 16; c++) {
        __syncthreads();
        s_a  [ar][ac] = pa;
        s_ea [ar][ac] = pea;
        s_bd [ar][ac] = pb;
        s_ebd[ar][ac] = peb;
        if (tid < 16) s_w[tid] = pw;
        __syncthreads();

        if (c < 15) {
            int oa = (c + 1) * 16 * (NN / 4);
            pa  = Ah2 [gja + oa];
            pea = EAh2[gja + oa];
            pb  = Bd4 [gib + oa];
            peb = EBd4[gib + oa];
            if (tid < 16) pw = Wh2[(c + 1) * 16 + tid];
        }

        #pragma unroll
        for (int h = 0; h < 2; h++) {
            __half2 accP[4][2], accE[4][2];
            #pragma unroll
            for (int i = 0; i < 4; i++)
                #pragma unroll
                for (int jp = 0; jp < 2; jp++) {
                    accP[i][jp] = __float2half2_rn(0.f);
                    accE[i][jp] = __float2half2_rn(0.f);
                }

            #pragma unroll
            for (int k8 = 0; k8 < 8; k8++) {
                const int kk = h * 8 + k8;
                uint2 ua  = s_a  [kk][tx];
                uint2 uea = s_ea [kk][tx];
                uint4 ub  = s_bd [kk][ty];
                uint4 ueb = s_ebd[kk][ty];
                uint2 uw  = s_w  [kk];

                __half2 a2 [2] = {*reinterpret_cast<__half2*>(&ua.x),
                                  *reinterpret_cast<__half2*>(&ua.y)};
                __half2 ea2[2] = {*reinterpret_cast<__half2*>(&uea.x),
                                  *reinterpret_cast<__half2*>(&uea.y)};
                __half2 bd [4] = {*reinterpret_cast<__half2*>(&ub.x),
                                  *reinterpret_cast<__half2*>(&ub.y),
                                  *reinterpret_cast<__half2*>(&ub.z),
                                  *reinterpret_cast<__half2*>(&ub.w)};
                __half2 ebd[4] = {*reinterpret_cast<__half2*>(&ueb.x),
                                  *reinterpret_cast<__half2*>(&ueb.y),
                                  *reinterpret_cast<__half2*>(&ueb.z),
                                  *reinterpret_cast<__half2*>(&ueb.w)};
                __half2 hw2 = *reinterpret_cast<__half2*>(&uw.x);
                __half2 aw2 = *reinterpret_cast<__half2*>(&uw.y);

                #pragma unroll
                for (int i = 0; i < 4; i++) {
                    #pragma unroll
                    for (int jp = 0; jp < 2; jp++) {
                        __half2 v = __habs2(__hadd2(a2[jp], bd[i]));
                        accP[i][jp] = __hfma2(v, hw2, accP[i][jp]);
                        __half2 e = __hmul2_sat(ea2[jp], ebd[i]);
                        accE[i][jp] = __hfma2(e, aw2, accE[i][jp]);
                    }
                }
            }

            // flush fp16 partials to fp32
            #pragma unroll
            for (int i = 0; i < 4; i++) {
                #pragma unroll
                for (int jp = 0; jp < 2; jp++) {
                    float2 f = __half22float2(__hadd2(accP[i][jp], accE[i][jp]));
                    accF[i][2 * jp]     += f.x;
                    accF[i][2 * jp + 1] += f.y;
                }
            }
        }
    }

    // epilogue: + P[j] + Q[i] + c0, hard_sigmoid
    const float c0 = g_c0;
    float4 Pv = *reinterpret_cast<const float4*>(&g_P[j0 + tx * 4]);
    #pragma unroll
    for (int i = 0; i < 4; i++) {
        int   irow = i0 + ty * 4 + i;
        float base = g_Q[irow] + c0 + 3.0f;
        float4 o;
        o.x = fminf(fmaxf(accF[i][0] + Pv.x + base, 0.f), 6.f) * (1.f / 6.f);
        o.y = fminf(fmaxf(accF[i][1] + Pv.y + base, 0.f), 6.f) * (1.f / 6.f);
        o.z = fminf(fmaxf(accF[i][2] + Pv.z + base, 0.f), 6.f) * (1.f / 6.f);
        o.w = fminf(fmaxf(accF[i][3] + Pv.w + base, 0.f), 6.f) * (1.f / 6.f);
        *reinterpret_cast<float4*>(&out[irow * NN + j0 + tx * 4]) = o;
    }
}

// ---------------------------------------------------------------------------
extern "C" void kernel_launch(void* const* d_in, const int* in_sizes, int n_in,
                              void* d_out, int out_size) {
    const float* x     = (const float*)d_in[0];
    const float* W_enc = (const float*)d_in[1];
    const float* b_enc = (const float*)d_in[2];
    const float* W1    = (const float*)d_in[3];
    const float* b1    = (const float*)d_in[4];
    const float* W2    = (const float*)d_in[5];
    const float* b2    = (const float*)d_in[6];
    float* out = (float*)d_out;

    aux_kernel<<<NN / 4, 256>>>(x, W_enc, b_enc, W1, b1, W2, b2);

    dim3 grid(NN / 64, NN / 64);
    main_kernel<<<grid, 256>>>(out);
}